// round 1
// baseline (speedup 1.0000x reference)
#include <cuda_runtime.h>
#include <cuda_bf16.h>
#include <math_constants.h>

// Problem constants
#define NPTS   32768      // B*H*W = 32*32*32
#define DIM    256        // channels
#define NCODE  8192       // codebook entries
#define HWSZ   1024       // H*W
#define ZQ_ELEMS (32*256*32*32)   // 8388608

// Tiling
#define BM 128            // points per block
#define BN 256            // codes per tile
#define BK 16             // d-chunk
#define TM 8              // points per thread
#define TNP 8             // code *pairs* per thread (16 codes)
#define ZSS 128           // zs row stride (floats)
#define ESS 260           // es row stride (floats), padded vs 256

#define SMEM_BYTES ((DIM*ZSS + 2*BK*ESS + BM + BM) * 4)

__device__ float g_enorm[NCODE];
__device__ int   g_best_idx[NPTS];

// ---------------- f32x2 helpers (Blackwell packed fp32) ----------------
__device__ __forceinline__ unsigned long long ffma2(unsigned long long a,
                                                    unsigned long long b,
                                                    unsigned long long c) {
    unsigned long long d;
    asm("fma.rn.f32x2 %0, %1, %2, %3;" : "=l"(d) : "l"(a), "l"(b), "l"(c));
    return d;
}
__device__ __forceinline__ unsigned long long dup2(float x) {
    unsigned long long r;
    asm("mov.b64 %0, {%1, %1};" : "=l"(r) : "f"(x));
    return r;
}
__device__ __forceinline__ void unpack2(unsigned long long v, float& lo, float& hi) {
    asm("mov.b64 {%0, %1}, %2;" : "=f"(lo), "=f"(hi) : "l"(v));
}

// ---------------- Kernel 0: codebook row norms ----------------
__global__ void k_enorm(const float* __restrict__ emb) {
    int warp = (blockIdx.x * blockDim.x + threadIdx.x) >> 5;
    int lane = threadIdx.x & 31;
    if (warp >= NCODE) return;
    const float4* r = reinterpret_cast<const float4*>(emb + (size_t)warp * DIM);
    float4 a = r[lane];
    float4 b = r[lane + 32];
    float s = a.x*a.x + a.y*a.y + a.z*a.z + a.w*a.w
            + b.x*b.x + b.y*b.y + b.z*b.z + b.w*b.w;
    #pragma unroll
    for (int off = 16; off > 0; off >>= 1)
        s += __shfl_xor_sync(0xffffffffu, s, off);
    if (lane == 0) g_enorm[warp] = s;
}

// ---------------- Kernel 1: GEMM + argmin ----------------
__global__ void __launch_bounds__(256, 1)
k_argmin(const float* __restrict__ z, const float* __restrict__ emb) {
    extern __shared__ float smem[];
    float* zs    = smem;                      // [DIM][ZSS]
    float* es    = smem + DIM * ZSS;          // [2][BK][ESS]
    float* bdist = es + 2 * BK * ESS;         // [BM]
    int*   bidx  = reinterpret_cast<int*>(bdist + BM);  // [BM]

    const int t  = threadIdx.x;
    const int tx = t & 15;          // code group (16 codes each)
    const int ty = t >> 4;          // point group (8 points each)

    const int n0  = blockIdx.x * BM;
    const int b   = n0 >> 10;
    const int hw0 = n0 & 1023;
    const float* zbase = z + ((size_t)b * DIM) * HWSZ + hw0;

    // Load this block's z tile once: zs[c][p] = z[b, c, hw0+p]
    #pragma unroll
    for (int i = t; i < DIM * (BM / 4); i += 256) {
        int c  = i >> 5;          // BM/4 = 32 float4 groups per row
        int pg = i & 31;
        float4 v = *reinterpret_cast<const float4*>(zbase + (size_t)c * HWSZ + pg * 4);
        *reinterpret_cast<float4*>(&zs[c * ZSS + pg * 4]) = v;
    }
    if (t < BM) { bdist[t] = CUDART_INF_F; bidx[t] = 0; }
    __syncthreads();

    unsigned long long acc[TM][TNP];
    float4 stage[4];

    for (int kt = 0; kt < NCODE; kt += BN) {
        #pragma unroll
        for (int p = 0; p < TM; ++p)
            #pragma unroll
            for (int u = 0; u < TNP; ++u)
                acc[p][u] = 0ull;

        const float* ebase = emb + (size_t)kt * DIM;

        // Prefetch chunk 0: chunk covers d-cols [ch*BK, ch*BK+16)
        #pragma unroll
        for (int i = 0; i < 4; ++i) {
            int s = t + i * 256;
            int code = s >> 2, cg = s & 3;
            stage[i] = *reinterpret_cast<const float4*>(
                ebase + (size_t)code * DIM + 0 * BK + cg * 4);
        }

        for (int ch = 0; ch < DIM / BK; ++ch) {
            float* eb = es + (ch & 1) * BK * ESS;
            // Commit staged chunk to smem (transposed: eb[c_local][code])
            #pragma unroll
            for (int i = 0; i < 4; ++i) {
                int s = t + i * 256;
                int code = s >> 2, cg = s & 3;
                eb[(cg * 4 + 0) * ESS + code] = stage[i].x;
                eb[(cg * 4 + 1) * ESS + code] = stage[i].y;
                eb[(cg * 4 + 2) * ESS + code] = stage[i].z;
                eb[(cg * 4 + 3) * ESS + code] = stage[i].w;
            }
            __syncthreads();
            if (ch < DIM / BK - 1) {
                int c0 = (ch + 1) * BK;
                #pragma unroll
                for (int i = 0; i < 4; ++i) {
                    int s = t + i * 256;
                    int code = s >> 2, cg = s & 3;
                    stage[i] = *reinterpret_cast<const float4*>(
                        ebase + (size_t)code * DIM + c0 + cg * 4);
                }
            }
            // Compute BK d-steps
            #pragma unroll
            for (int s = 0; s < BK; ++s) {
                int c = ch * BK + s;
                float4 za = *reinterpret_cast<const float4*>(&zs[c * ZSS + ty * TM]);
                float4 zb = *reinterpret_cast<const float4*>(&zs[c * ZSS + ty * TM + 4]);
                unsigned long long z2[TM];
                z2[0] = dup2(za.x); z2[1] = dup2(za.y);
                z2[2] = dup2(za.z); z2[3] = dup2(za.w);
                z2[4] = dup2(zb.x); z2[5] = dup2(zb.y);
                z2[6] = dup2(zb.z); z2[7] = dup2(zb.w);
                const ulonglong2* ep =
                    reinterpret_cast<const ulonglong2*>(&eb[s * ESS + tx * 16]);
                ulonglong2 e0 = ep[0], e1 = ep[1], e2 = ep[2], e3 = ep[3];
                unsigned long long ee[TNP] = {e0.x, e0.y, e1.x, e1.y,
                                              e2.x, e2.y, e3.x, e3.y};
                #pragma unroll
                for (int p = 0; p < TM; ++p)
                    #pragma unroll
                    for (int u = 0; u < TNP; ++u)
                        acc[p][u] = ffma2(z2[p], ee[u], acc[p][u]);
            }
            __syncthreads();
        }

        // Epilogue: dist = enorm[k] - 2*dot ; argmin with lowest-index tie-break
        float en[16];
        {
            const float4* e4 = reinterpret_cast<const float4*>(g_enorm + kt + tx * 16);
            float4 a = e4[0], bb = e4[1], cc = e4[2], dd = e4[3];
            en[0]=a.x; en[1]=a.y; en[2]=a.z; en[3]=a.w;
            en[4]=bb.x; en[5]=bb.y; en[6]=bb.z; en[7]=bb.w;
            en[8]=cc.x; en[9]=cc.y; en[10]=cc.z; en[11]=cc.w;
            en[12]=dd.x; en[13]=dd.y; en[14]=dd.z; en[15]=dd.w;
        }
        int kbase = kt + tx * 16;
        #pragma unroll
        for (int p = 0; p < TM; ++p) {
            float bd = CUDART_INF_F;
            int bk = 0x7fffffff;
            #pragma unroll
            for (int u = 0; u < TNP; ++u) {
                float lo, hi;
                unpack2(acc[p][u], lo, hi);
                float d0 = fmaf(-2.0f, lo, en[2 * u]);
                float d1 = fmaf(-2.0f, hi, en[2 * u + 1]);
                if (d0 < bd) { bd = d0; bk = kbase + 2 * u; }
                if (d1 < bd) { bd = d1; bk = kbase + 2 * u + 1; }
            }
            #pragma unroll
            for (int off = 8; off > 0; off >>= 1) {
                float od = __shfl_xor_sync(0xffffffffu, bd, off);
                int   ok = __shfl_xor_sync(0xffffffffu, bk, off);
                if (od < bd || (od == bd && ok < bk)) { bd = od; bk = ok; }
            }
            if (tx == 0) {
                int pi = ty * TM + p;
                if (bd < bdist[pi]) { bdist[pi] = bd; bidx[pi] = bk; }
            }
        }
    }
    __syncthreads();
    if (t < BM) g_best_idx[n0 + t] = bidx[t];
}

// ---------------- Kernel 2: output writer ----------------
// z_q[b,c,h,w] = z + (emb[idx,c] - z)  (replicating the straight-through fp32 math)
// Tail (if present): indices as float.
__global__ void k_write(const float* __restrict__ z, const float* __restrict__ emb,
                        float* __restrict__ out, int out_size) {
    int i = blockIdx.x * 256 + threadIdx.x;
    if (i >= out_size) return;
    if (i < ZQ_ELEMS) {
        int hw = i & 1023;
        int bc = i >> 10;
        int c  = bc & 255;
        int b  = bc >> 8;
        int n  = (b << 10) + hw;
        int k  = g_best_idx[n];
        float e  = emb[(size_t)k * DIM + c];
        float zv = z[i];
        out[i] = __fadd_rn(zv, __fsub_rn(e, zv));
    } else {
        int j = i - ZQ_ELEMS;
        out[i] = (j < NPTS) ? (float)g_best_idx[j] : 0.0f;
    }
}

extern "C" void kernel_launch(void* const* d_in, const int* in_sizes, int n_in,
                              void* d_out, int out_size) {
    // Disambiguate input order by size (z has 8388608 elems, embedding 2097152)
    const float* z   = (const float*)d_in[0];
    const float* emb = (const float*)d_in[1];
    if (in_sizes[0] != ZQ_ELEMS) {
        const float* tmp = z; z = emb; emb = tmp;
    }
    float* out = (float*)d_out;

    cudaFuncSetAttribute(k_argmin, cudaFuncAttributeMaxDynamicSharedMemorySize,
                         SMEM_BYTES);

    k_enorm<<<NCODE / 8, 256>>>(emb);
    k_argmin<<<NPTS / BM, 256, SMEM_BYTES>>>(z, emb);
    int wgrid = (out_size + 255) / 256;
    k_write<<<wgrid, 256>>>(z, emb, out, out_size);
}

// round 2
// speedup vs baseline: 1.0002x; 1.0002x over previous
#include <cuda_runtime.h>
#include <cuda_bf16.h>
#include <math_constants.h>

// Problem constants
#define NPTS   32768      // B*H*W = 32*32*32
#define DIM    256        // channels
#define NCODE  8192       // codebook entries
#define HWSZ   1024       // H*W
#define ZQ_ELEMS (32*256*32*32)   // 8388608

// Tiling
#define BM 128            // points per block
#define BN 256            // codes per tile
#define BK 16             // d-chunk
#define TM 8              // points per thread
#define TNP 8             // code *pairs* per thread (16 codes)
#define ZSS 128           // zs row stride (floats)
#define ESS 260           // es row stride (floats), padded vs 256

#define SMEM_BYTES ((DIM*ZSS + 2*BK*ESS + BM + BM) * 4)

__device__ float g_enorm[NCODE];
__device__ int   g_best_idx[NPTS];

// ---------------- f32x2 helpers (Blackwell packed fp32) ----------------
__device__ __forceinline__ unsigned long long ffma2(unsigned long long a,
                                                    unsigned long long b,
                                                    unsigned long long c) {
    unsigned long long d;
    asm("fma.rn.f32x2 %0, %1, %2, %3;" : "=l"(d) : "l"(a), "l"(b), "l"(c));
    return d;
}
__device__ __forceinline__ unsigned long long dup2(float x) {
    unsigned long long r;
    asm("mov.b64 %0, {%1, %1};" : "=l"(r) : "f"(x));
    return r;
}
__device__ __forceinline__ void unpack2(unsigned long long v, float& lo, float& hi) {
    asm("mov.b64 {%0, %1}, %2;" : "=f"(lo), "=f"(hi) : "l"(v));
}

// ---------------- Kernel 0: codebook row norms ----------------
__global__ void k_enorm(const float* __restrict__ emb) {
    int warp = (blockIdx.x * blockDim.x + threadIdx.x) >> 5;
    int lane = threadIdx.x & 31;
    if (warp >= NCODE) return;
    const float4* r = reinterpret_cast<const float4*>(emb + (size_t)warp * DIM);
    float4 a = r[lane];
    float4 b = r[lane + 32];
    float s = a.x*a.x + a.y*a.y + a.z*a.z + a.w*a.w
            + b.x*b.x + b.y*b.y + b.z*b.z + b.w*b.w;
    #pragma unroll
    for (int off = 16; off > 0; off >>= 1)
        s += __shfl_xor_sync(0xffffffffu, s, off);
    if (lane == 0) g_enorm[warp] = s;
}

// ---------------- Kernel 1: GEMM + argmin ----------------
__global__ void __launch_bounds__(256, 1)
k_argmin(const float* __restrict__ z, const float* __restrict__ emb) {
    extern __shared__ float smem[];
    float* zs    = smem;                      // [DIM][ZSS]
    float* es    = smem + DIM * ZSS;          // [2][BK][ESS]
    float* bdist = es + 2 * BK * ESS;         // [BM]
    int*   bidx  = reinterpret_cast<int*>(bdist + BM);  // [BM]

    const int t  = threadIdx.x;
    const int tx = t & 15;          // code group (16 codes each)
    const int ty = t >> 4;          // point group (8 points each)

    const int n0  = blockIdx.x * BM;
    const int b   = n0 >> 10;
    const int hw0 = n0 & 1023;
    const float* zbase = z + ((size_t)b * DIM) * HWSZ + hw0;

    // Load this block's z tile once: zs[c][p] = z[b, c, hw0+p]
    #pragma unroll
    for (int i = t; i < DIM * (BM / 4); i += 256) {
        int c  = i >> 5;          // BM/4 = 32 float4 groups per row
        int pg = i & 31;
        float4 v = *reinterpret_cast<const float4*>(zbase + (size_t)c * HWSZ + pg * 4);
        *reinterpret_cast<float4*>(&zs[c * ZSS + pg * 4]) = v;
    }
    if (t < BM) { bdist[t] = CUDART_INF_F; bidx[t] = 0; }
    __syncthreads();

    unsigned long long acc[TM][TNP];
    float4 stage[4];

    for (int kt = 0; kt < NCODE; kt += BN) {
        #pragma unroll
        for (int p = 0; p < TM; ++p)
            #pragma unroll
            for (int u = 0; u < TNP; ++u)
                acc[p][u] = 0ull;

        const float* ebase = emb + (size_t)kt * DIM;

        // Prefetch chunk 0: chunk covers d-cols [ch*BK, ch*BK+16)
        #pragma unroll
        for (int i = 0; i < 4; ++i) {
            int s = t + i * 256;
            int code = s >> 2, cg = s & 3;
            stage[i] = *reinterpret_cast<const float4*>(
                ebase + (size_t)code * DIM + 0 * BK + cg * 4);
        }

        for (int ch = 0; ch < DIM / BK; ++ch) {
            float* eb = es + (ch & 1) * BK * ESS;
            // Commit staged chunk to smem (transposed: eb[c_local][code])
            #pragma unroll
            for (int i = 0; i < 4; ++i) {
                int s = t + i * 256;
                int code = s >> 2, cg = s & 3;
                eb[(cg * 4 + 0) * ESS + code] = stage[i].x;
                eb[(cg * 4 + 1) * ESS + code] = stage[i].y;
                eb[(cg * 4 + 2) * ESS + code] = stage[i].z;
                eb[(cg * 4 + 3) * ESS + code] = stage[i].w;
            }
            __syncthreads();
            if (ch < DIM / BK - 1) {
                int c0 = (ch + 1) * BK;
                #pragma unroll
                for (int i = 0; i < 4; ++i) {
                    int s = t + i * 256;
                    int code = s >> 2, cg = s & 3;
                    stage[i] = *reinterpret_cast<const float4*>(
                        ebase + (size_t)code * DIM + c0 + cg * 4);
                }
            }
            // Compute BK d-steps
            #pragma unroll
            for (int s = 0; s < BK; ++s) {
                int c = ch * BK + s;
                float4 za = *reinterpret_cast<const float4*>(&zs[c * ZSS + ty * TM]);
                float4 zb = *reinterpret_cast<const float4*>(&zs[c * ZSS + ty * TM + 4]);
                unsigned long long z2[TM];
                z2[0] = dup2(za.x); z2[1] = dup2(za.y);
                z2[2] = dup2(za.z); z2[3] = dup2(za.w);
                z2[4] = dup2(zb.x); z2[5] = dup2(zb.y);
                z2[6] = dup2(zb.z); z2[7] = dup2(zb.w);
                const ulonglong2* ep =
                    reinterpret_cast<const ulonglong2*>(&eb[s * ESS + tx * 16]);
                ulonglong2 e0 = ep[0], e1 = ep[1], e2 = ep[2], e3 = ep[3];
                unsigned long long ee[TNP] = {e0.x, e0.y, e1.x, e1.y,
                                              e2.x, e2.y, e3.x, e3.y};
                #pragma unroll
                for (int p = 0; p < TM; ++p)
                    #pragma unroll
                    for (int u = 0; u < TNP; ++u)
                        acc[p][u] = ffma2(z2[p], ee[u], acc[p][u]);
            }
            __syncthreads();
        }

        // Epilogue: dist = enorm[k] - 2*dot ; argmin with lowest-index tie-break
        float en[16];
        {
            const float4* e4 = reinterpret_cast<const float4*>(g_enorm + kt + tx * 16);
            float4 a = e4[0], bb = e4[1], cc = e4[2], dd = e4[3];
            en[0]=a.x; en[1]=a.y; en[2]=a.z; en[3]=a.w;
            en[4]=bb.x; en[5]=bb.y; en[6]=bb.z; en[7]=bb.w;
            en[8]=cc.x; en[9]=cc.y; en[10]=cc.z; en[11]=cc.w;
            en[12]=dd.x; en[13]=dd.y; en[14]=dd.z; en[15]=dd.w;
        }
        int kbase = kt + tx * 16;
        #pragma unroll
        for (int p = 0; p < TM; ++p) {
            float bd = CUDART_INF_F;
            int bk = 0x7fffffff;
            #pragma unroll
            for (int u = 0; u < TNP; ++u) {
                float lo, hi;
                unpack2(acc[p][u], lo, hi);
                float d0 = fmaf(-2.0f, lo, en[2 * u]);
                float d1 = fmaf(-2.0f, hi, en[2 * u + 1]);
                if (d0 < bd) { bd = d0; bk = kbase + 2 * u; }
                if (d1 < bd) { bd = d1; bk = kbase + 2 * u + 1; }
            }
            #pragma unroll
            for (int off = 8; off > 0; off >>= 1) {
                float od = __shfl_xor_sync(0xffffffffu, bd, off);
                int   ok = __shfl_xor_sync(0xffffffffu, bk, off);
                if (od < bd || (od == bd && ok < bk)) { bd = od; bk = ok; }
            }
            if (tx == 0) {
                int pi = ty * TM + p;
                if (bd < bdist[pi]) { bdist[pi] = bd; bidx[pi] = bk; }
            }
        }
    }
    __syncthreads();
    if (t < BM) g_best_idx[n0 + t] = bidx[t];
}

// ---------------- Kernel 2: output writer ----------------
// z_q[b,c,h,w] = z + (emb[idx,c] - z)  (replicating the straight-through fp32 math)
// Tail (if present): indices as float.
__global__ void k_write(const float* __restrict__ z, const float* __restrict__ emb,
                        float* __restrict__ out, int out_size) {
    int i = blockIdx.x * 256 + threadIdx.x;
    if (i >= out_size) return;
    if (i < ZQ_ELEMS) {
        int hw = i & 1023;
        int bc = i >> 10;
        int c  = bc & 255;
        int b  = bc >> 8;
        int n  = (b << 10) + hw;
        int k  = g_best_idx[n];
        float e  = emb[(size_t)k * DIM + c];
        float zv = z[i];
        out[i] = __fadd_rn(zv, __fsub_rn(e, zv));
    } else {
        int j = i - ZQ_ELEMS;
        out[i] = (j < NPTS) ? (float)g_best_idx[j] : 0.0f;
    }
}

extern "C" void kernel_launch(void* const* d_in, const int* in_sizes, int n_in,
                              void* d_out, int out_size) {
    // Disambiguate input order by size (z has 8388608 elems, embedding 2097152)
    const float* z   = (const float*)d_in[0];
    const float* emb = (const float*)d_in[1];
    if (in_sizes[0] != ZQ_ELEMS) {
        const float* tmp = z; z = emb; emb = tmp;
    }
    float* out = (float*)d_out;

    cudaFuncSetAttribute(k_argmin, cudaFuncAttributeMaxDynamicSharedMemorySize,
                         SMEM_BYTES);

    k_enorm<<<NCODE / 8, 256>>>(emb);
    k_argmin<<<NPTS / BM, 256, SMEM_BYTES>>>(z, emb);
    int wgrid = (out_size + 255) / 256;
    k_write<<<wgrid, 256>>>(z, emb, out, out_size);
}